// round 6
// baseline (speedup 1.0000x reference)
#include <cuda_runtime.h>
#include <math.h>
#include <stdint.h>

// Problem shape (fixed): B=512, L=512, D=256, fp32.
#define BATCH 512
#define LDIM  512
#define DDIM  256
#define EPSV  1e-6f

#define CTM 128
#define CTN 128
#define KCH 32               // K elements staged per chunk
#define NCHUNK (DDIM/KCH)    // 8
#define RS 48                // smem row stride (== 16 mod 32 -> conflict-free LDS.128)

// smem (floats): As[2][128][RS] | Bs[2][128][RS] | r1[128] | r2[128]
#define TILEF (128*RS)                   // 6144
#define AS_OFF(s) ((s)*TILEF)
#define BS_OFF(s) (2*TILEF + (s)*TILEF)
#define R1_OFF   (4*TILEF)
#define R2_OFF   (4*TILEF + 128)
#define SMEM_FLOATS (4*TILEF + 256)
#define SMEM_BYTES  (SMEM_FLOATS*4)      // 99,328 B -> 2 CTAs/SM (194KB/SM)

__device__ __forceinline__ uint32_t smem_u32(const void* p) {
    uint32_t a;
    asm("{ .reg .u64 t; cvta.to.shared.u64 t, %1; cvt.u32.u64 %0, t; }" : "=r"(a) : "l"(p));
    return a;
}
__device__ __forceinline__ float fsqrt_fast(float x) {
    float y; asm("sqrt.approx.f32 %0, %1;" : "=f"(y) : "f"(x)); return y;
}
__device__ __forceinline__ void cp16(uint32_t saddr, const float* g) {
    asm volatile("cp.async.cg.shared.global [%0], [%1], 16;" :: "r"(saddr), "l"(g));
}
__device__ __forceinline__ void cp_commit() { asm volatile("cp.async.commit_group;"); }
__device__ __forceinline__ void cp_wait1()  { asm volatile("cp.async.wait_group 1;" ::: "memory"); }
__device__ __forceinline__ void cp_wait0()  { asm volatile("cp.async.wait_group 0;" ::: "memory"); }

__device__ __forceinline__ void mma_tf32(float* c,
                                         uint32_t a0, uint32_t a1, uint32_t a2, uint32_t a3,
                                         uint32_t b0, uint32_t b1) {
    asm volatile(
        "mma.sync.aligned.m16n8k8.row.col.f32.tf32.tf32.f32 "
        "{%0,%1,%2,%3}, {%4,%5,%6,%7}, {%8,%9}, {%0,%1,%2,%3};"
        : "+f"(c[0]), "+f"(c[1]), "+f"(c[2]), "+f"(c[3])
        : "r"(a0), "r"(a1), "r"(a2), "r"(a3), "r"(b0), "r"(b1));
}

// ---------------------------------------------------------------------------
__global__ __launch_bounds__(256, 2)
void dist_tf32_kernel(const float* __restrict__ A, const float* __restrict__ B,
                      float* __restrict__ out) {
    extern __shared__ float smf[];
    const uint32_t sbase = smem_u32(smf);

    const int tid = threadIdx.x;
    const int wid = tid >> 5, lid = tid & 31;
    const int b  = blockIdx.z;
    const int m0 = blockIdx.y * CTM;
    const int n0 = blockIdx.x * CTN;

    // ---- cp.async mapping: 4 rows/warp/step, 8 lanes cover a 128B row chunk
    const int crow = (wid << 2) + (lid >> 3);
    const int cc   = (lid & 7) * 4;
    const float* Ag = A + ((size_t)(b * LDIM + m0 + crow)) * DDIM + cc;
    const float* Bg = B + ((size_t)(b * LDIM + n0 + crow)) * DDIM + cc;
    const uint32_t sA0 = sbase + 4u * (uint32_t)(crow * RS + cc);
    const uint32_t sB0 = sA0 + 4u * (uint32_t)(2 * TILEF);

    // ---- norm mapping: 2 threads per row ----
    const int nrow = tid >> 1;
    const int h    = tid & 1;
    const int j0   = (nrow & 3) * 4;

    // ---- compute mapping: 2x4 warp grid, 64x32 warp tiles ----
    const int wm = wid >> 2;
    const int wn = wid & 3;
    const int g   = lid >> 2;
    const int tig = lid & 3;
    const int klane = 2 * tig;
    const int arow0 = wm * 64 + g;
    const int brow0 = wn * 32 + g;

    float acc[4][4][4];
#pragma unroll
    for (int mt = 0; mt < 4; mt++)
#pragma unroll
        for (int nt = 0; nt < 4; nt++)
#pragma unroll
            for (int r = 0; r < 4; r++) acc[mt][nt][r] = 0.f;

    float ssa = 0.f, sa = 0.f, ssb = 0.f, sB2 = 0.f;

    // ---- stage chunks 0 and 1 ----
#pragma unroll
    for (int s = 0; s < 2; s++) {
#pragma unroll
        for (int t = 0; t < 4; t++) {
            cp16(sA0 + 4u * (uint32_t)(s * TILEF + t * 32 * RS), Ag + (size_t)(t * 32) * DDIM + s * KCH);
            cp16(sB0 + 4u * (uint32_t)(s * TILEF + t * 32 * RS), Bg + (size_t)(t * 32) * DDIM + s * KCH);
        }
        cp_commit();
    }

#pragma unroll 1
    for (int kt = 0; kt < NCHUNK; kt++) {
        const int buf = kt & 1;
        if (kt == NCHUNK - 1) cp_wait0(); else cp_wait1();
        __syncthreads();

        const float* As = &smf[AS_OFF(buf)];
        const float* Bs = &smf[BS_OFF(buf)];

        // ---- norms from staged fp32 (rotation -> conflict-free) ----
        {
            const float* nA = As + nrow * RS + h * 16;
            const float* nB = Bs + nrow * RS + h * 16;
#pragma unroll
            for (int t = 0; t < 4; t++) {
                int o = (j0 + 4 * t) & 15;
                float4 a = *reinterpret_cast<const float4*>(nA + o);
                float4 v = *reinterpret_cast<const float4*>(nB + o);
                ssa = fmaf(a.x, a.x, ssa); ssa = fmaf(a.y, a.y, ssa);
                ssa = fmaf(a.z, a.z, ssa); ssa = fmaf(a.w, a.w, ssa);
                sa += a.x + a.y + a.z + a.w;
                ssb = fmaf(v.x, v.x, ssb); ssb = fmaf(v.y, v.y, ssb);
                ssb = fmaf(v.z, v.z, ssb); ssb = fmaf(v.w, v.w, ssb);
                sB2 += v.x + v.y + v.z + v.w;
            }
        }

        // ---- MMA: 2 x k16 blocks; one LDS.128 feeds two k8 HMMA steps.
        // Thread tig owns k-quad {4tig..4tig+3} (consistent A/B k-permutation).
        const float* Aw = As + arow0 * RS + 4 * tig;
        const float* Bw = Bs + brow0 * RS + 4 * tig;
#pragma unroll
        for (int blk = 0; blk < 2; blk++) {
            uint4 bf[4];
#pragma unroll
            for (int nt = 0; nt < 4; nt++)
                bf[nt] = *reinterpret_cast<const uint4*>(Bw + nt * 8 * RS + 16 * blk);
#pragma unroll
            for (int mt = 0; mt < 4; mt++) {
                uint4 alo = *reinterpret_cast<const uint4*>(Aw + (mt * 16) * RS + 16 * blk);
                uint4 ahi = *reinterpret_cast<const uint4*>(Aw + (mt * 16 + 8) * RS + 16 * blk);
#pragma unroll
                for (int nt = 0; nt < 4; nt++) {
                    mma_tf32(acc[mt][nt], alo.x, ahi.x, alo.y, ahi.y, bf[nt].x, bf[nt].y);
                    mma_tf32(acc[mt][nt], alo.z, ahi.z, alo.w, ahi.w, bf[nt].z, bf[nt].w);
                }
            }
        }

        __syncthreads();   // all reads of buf done before restaging into it

        if (kt + 2 < NCHUNK) {
            const int nk = kt + 2;
#pragma unroll
            for (int t = 0; t < 4; t++) {
                cp16(sA0 + 4u * (uint32_t)(buf * TILEF + t * 32 * RS), Ag + (size_t)(t * 32) * DDIM + nk * KCH);
                cp16(sB0 + 4u * (uint32_t)(buf * TILEF + t * 32 * RS), Bg + (size_t)(t * 32) * DDIM + nk * KCH);
            }
            cp_commit();
        }
    }

    // ---- norms: combine thread pair (tid, tid^1), publish to smem ----
    ssa += __shfl_xor_sync(0xffffffffu, ssa, 1);
    sa  += __shfl_xor_sync(0xffffffffu, sa, 1);
    ssb += __shfl_xor_sync(0xffffffffu, ssb, 1);
    sB2 += __shfl_xor_sync(0xffffffffu, sB2, 1);
    if (h == 0) {
        smf[R1_OFF + nrow] = ssa + 2.0f * EPSV * sa;
        smf[R2_OFF + nrow] = ssb - 2.0f * EPSV * sB2 + (float)DDIM * EPSV * EPSV;
    }
    __syncthreads();

    // ---- epilogue: d = sqrt(max(r1 + r2 - 2*dot, 0)), float2 stores ----
    float r1v[4][2];
#pragma unroll
    for (int mt = 0; mt < 4; mt++) {
        r1v[mt][0] = smf[R1_OFF + wm * 64 + mt * 16 + g];
        r1v[mt][1] = smf[R1_OFF + wm * 64 + mt * 16 + g + 8];
    }
    float2 r2v[4];
#pragma unroll
    for (int nt = 0; nt < 4; nt++)
        r2v[nt] = *reinterpret_cast<const float2*>(&smf[R2_OFF + wn * 32 + nt * 8 + klane]);

    float* Ob = out + ((size_t)(b * LDIM + m0)) * LDIM + n0;
#pragma unroll
    for (int mt = 0; mt < 4; mt++) {
#pragma unroll
        for (int nt = 0; nt < 4; nt++) {
            const int col  = wn * 32 + nt * 8 + klane;
            const int row0 = wm * 64 + mt * 16 + g;
            float2 v0, v1;
            v0.x = fsqrt_fast(fmaxf(r1v[mt][0] + r2v[nt].x - 2.0f * acc[mt][nt][0], 0.f));
            v0.y = fsqrt_fast(fmaxf(r1v[mt][0] + r2v[nt].y - 2.0f * acc[mt][nt][1], 0.f));
            v1.x = fsqrt_fast(fmaxf(r1v[mt][1] + r2v[nt].x - 2.0f * acc[mt][nt][2], 0.f));
            v1.y = fsqrt_fast(fmaxf(r1v[mt][1] + r2v[nt].y - 2.0f * acc[mt][nt][3], 0.f));
            *reinterpret_cast<float2*>(Ob + (size_t)row0 * LDIM + col)       = v0;
            *reinterpret_cast<float2*>(Ob + (size_t)(row0 + 8) * LDIM + col) = v1;
        }
    }
}

// ---------------------------------------------------------------------------
extern "C" void kernel_launch(void* const* d_in, const int* in_sizes, int n_in,
                              void* d_out, int out_size) {
    const float* A = (const float*)d_in[0];
    const float* B = (const float*)d_in[1];
    float* out = (float*)d_out;
    (void)in_sizes; (void)n_in; (void)out_size;

    cudaFuncSetAttribute(dist_tf32_kernel,
                         cudaFuncAttributeMaxDynamicSharedMemorySize, SMEM_BYTES);
    dim3 grid(LDIM / CTN, LDIM / CTM, BATCH);
    dist_tf32_kernel<<<grid, 256, SMEM_BYTES>>>(A, B, out);
}

// round 7
// speedup vs baseline: 1.0845x; 1.0845x over previous
#include <cuda_runtime.h>
#include <math.h>
#include <stdint.h>

// Problem shape (fixed): B=512, L=512, D=256, fp32.
#define BATCH 512
#define LDIM  512
#define DDIM  256
#define EPSV  1e-6f

#define CTM 128
#define CTN 128
#define KCH 32               // K elements staged per chunk
#define NCHUNK (DDIM/KCH)    // 8
#define NST 3                // pipeline stages

// Swizzled tile: 128 rows x 32 floats (128B row), 16B chunks permuted by
// key(row) = ((row&3)<<1) | ((row>>2)&1)  (chunk' = chunk ^ key).
#define TILEF 4096                         // floats per tile (16KB)
#define AS_OFF(s) ((s)*TILEF)              // A stages 0..2
#define BS_OFF(s) (3*TILEF + (s)*TILEF)    // B stages 0..2
#define R1_OFF   (6*TILEF)
#define R2_OFF   (6*TILEF + 128)
#define SMEM_FLOATS (6*TILEF + 256)
#define SMEM_BYTES  (SMEM_FLOATS*4)        // 99,328 B -> 2 CTAs/SM

__device__ __forceinline__ uint32_t smem_u32(const void* p) {
    uint32_t a;
    asm("{ .reg .u64 t; cvta.to.shared.u64 t, %1; cvt.u32.u64 %0, t; }" : "=r"(a) : "l"(p));
    return a;
}
__device__ __forceinline__ float fsqrt_fast(float x) {
    float y; asm("sqrt.approx.f32 %0, %1;" : "=f"(y) : "f"(x)); return y;
}
__device__ __forceinline__ void cp16(uint32_t saddr, const float* g) {
    asm volatile("cp.async.cg.shared.global [%0], [%1], 16;" :: "r"(saddr), "l"(g));
}
__device__ __forceinline__ void cp_commit() { asm volatile("cp.async.commit_group;"); }
__device__ __forceinline__ void cp_wait1()  { asm volatile("cp.async.wait_group 1;" ::: "memory"); }
__device__ __forceinline__ void cp_wait0()  { asm volatile("cp.async.wait_group 0;" ::: "memory"); }

__device__ __forceinline__ void mma_tf32(float* c,
                                         uint32_t a0, uint32_t a1, uint32_t a2, uint32_t a3,
                                         uint32_t b0, uint32_t b1) {
    asm volatile(
        "mma.sync.aligned.m16n8k8.row.col.f32.tf32.tf32.f32 "
        "{%0,%1,%2,%3}, {%4,%5,%6,%7}, {%8,%9}, {%0,%1,%2,%3};"
        : "+f"(c[0]), "+f"(c[1]), "+f"(c[2]), "+f"(c[3])
        : "r"(a0), "r"(a1), "r"(a2), "r"(a3), "r"(b0), "r"(b1));
}

// ---------------------------------------------------------------------------
__global__ __launch_bounds__(256, 2)
void dist_tf32_kernel(const float* __restrict__ A, const float* __restrict__ B,
                      float* __restrict__ out) {
    extern __shared__ float smf[];
    const uint32_t sbase = smem_u32(smf);

    const int tid = threadIdx.x;
    const int wid = tid >> 5, lid = tid & 31;
    const int b  = blockIdx.z;
    const int m0 = blockIdx.y * CTM;
    const int n0 = blockIdx.x * CTN;

    // ---- cp.async mapping: 4 rows/warp/step, 8 lanes per 128B row ----
    const int crow = (wid << 2) + (lid >> 3);
    const int cch  = lid & 7;                              // 16B chunk index
    const int kcy  = ((crow & 3) << 1) | ((crow >> 2) & 1);
    const uint32_t cpOff = (uint32_t)(crow * 128 + ((cch ^ kcy) << 4));
    const float* Ag = A + ((size_t)(b * LDIM + m0 + crow)) * DDIM + cch * 4;
    const float* Bg = B + ((size_t)(b * LDIM + n0 + crow)) * DDIM + cch * 4;

    // ---- norm mapping: 2 threads per row ----
    const int nrow = tid >> 1;
    const int h    = tid & 1;
    const int kn   = ((nrow & 3) << 1) | ((nrow >> 2) & 1);

    // ---- compute mapping: 2x4 warp grid, 64x32 warp tiles ----
    const int wm = wid >> 2;
    const int wn = wid & 3;
    const int g   = lid >> 2;
    const int tig = lid & 3;
    const int klane = 2 * tig;
    const int arow0 = wm * 64 + g;
    const int brow0 = wn * 32 + g;
    const int kg  = ((g & 3) << 1) | ((g >> 2) & 1);       // swizzle key (row&7 == g)
    const int u   = tig >> 1;                              // chunk sub-index
    const int w2  = 2 * (tig & 1);                         // intra-chunk float offset

    float acc[4][4][4];
#pragma unroll
    for (int mt = 0; mt < 4; mt++)
#pragma unroll
        for (int nt = 0; nt < 4; nt++)
#pragma unroll
            for (int r = 0; r < 4; r++) acc[mt][nt][r] = 0.f;

    float ssa = 0.f, sa = 0.f, ssb = 0.f, sB2 = 0.f;

    // ---- prologue: stage chunks 0 and 1 into stages 0 and 1 ----
#pragma unroll
    for (int s = 0; s < 2; s++) {
#pragma unroll
        for (int t = 0; t < 4; t++) {
            cp16(sbase + 4u * (uint32_t)AS_OFF(s) + (uint32_t)(t * 4096) + cpOff,
                 Ag + (size_t)(t * 32) * DDIM + s * KCH);
            cp16(sbase + 4u * (uint32_t)BS_OFF(s) + (uint32_t)(t * 4096) + cpOff,
                 Bg + (size_t)(t * 32) * DDIM + s * KCH);
        }
        cp_commit();
    }

    int stage = 0;
#pragma unroll 1
    for (int kt = 0; kt < NCHUNK; kt++) {
        if (kt == NCHUNK - 1) cp_wait0(); else cp_wait1();
        __syncthreads();   // single barrier per chunk

        // ---- prefetch chunk kt+2 into stage (stage+2)%3 (consumed at kt-1) ----
        if (kt + 2 < NCHUNK) {
            const int cst = (stage == 0) ? 2 : stage - 1;
            const int nk  = kt + 2;
#pragma unroll
            for (int t = 0; t < 4; t++) {
                cp16(sbase + 4u * (uint32_t)AS_OFF(cst) + (uint32_t)(t * 4096) + cpOff,
                     Ag + (size_t)(t * 32) * DDIM + nk * KCH);
                cp16(sbase + 4u * (uint32_t)BS_OFF(cst) + (uint32_t)(t * 4096) + cpOff,
                     Bg + (size_t)(t * 32) * DDIM + nk * KCH);
            }
            cp_commit();
        }

        const float* As = &smf[AS_OFF(stage)];
        const float* Bs = &smf[BS_OFF(stage)];

        // ---- norms from staged fp32 (swizzle-aware; order-independent sums) ----
        {
            const float* nA = As + nrow * 32;
            const float* nB = Bs + nrow * 32;
#pragma unroll
            for (int t = 0; t < 4; t++) {
                int c = ((4 * h + t) ^ kn) << 2;
                float4 a = *reinterpret_cast<const float4*>(nA + c);
                float4 v = *reinterpret_cast<const float4*>(nB + c);
                ssa = fmaf(a.x, a.x, ssa); ssa = fmaf(a.y, a.y, ssa);
                ssa = fmaf(a.z, a.z, ssa); ssa = fmaf(a.w, a.w, ssa);
                sa += a.x + a.y + a.z + a.w;
                ssb = fmaf(v.x, v.x, ssb); ssb = fmaf(v.y, v.y, ssb);
                ssb = fmaf(v.z, v.z, ssb); ssb = fmaf(v.w, v.w, ssb);
                sB2 += v.x + v.y + v.z + v.w;
            }
        }

        // ---- MMA: 4 k8-steps; thread tig owns k pair {4u+w2, +1} per k8 block
        //      (consistent A/B k-relabeling -> dot invariant) ----
#pragma unroll
        for (int s = 0; s < 4; s++) {
            const int ch = ((2 * s + u) ^ kg) << 2;        // swizzled chunk -> float idx
            uint2 afr[4][2], bfr[4];
#pragma unroll
            for (int mt = 0; mt < 4; mt++) {
                afr[mt][0] = *reinterpret_cast<const uint2*>(&As[(arow0 + mt * 16) * 32 + ch + w2]);
                afr[mt][1] = *reinterpret_cast<const uint2*>(&As[(arow0 + mt * 16 + 8) * 32 + ch + w2]);
            }
#pragma unroll
            for (int nt = 0; nt < 4; nt++)
                bfr[nt] = *reinterpret_cast<const uint2*>(&Bs[(brow0 + nt * 8) * 32 + ch + w2]);
#pragma unroll
            for (int mt = 0; mt < 4; mt++)
#pragma unroll
                for (int nt = 0; nt < 4; nt++)
                    mma_tf32(acc[mt][nt],
                             afr[mt][0].x, afr[mt][1].x, afr[mt][0].y, afr[mt][1].y,
                             bfr[nt].x, bfr[nt].y);
        }

        stage = (stage == 2) ? 0 : stage + 1;
    }

    // ---- norms: combine thread pair (tid, tid^1), publish to smem ----
    ssa += __shfl_xor_sync(0xffffffffu, ssa, 1);
    sa  += __shfl_xor_sync(0xffffffffu, sa, 1);
    ssb += __shfl_xor_sync(0xffffffffu, ssb, 1);
    sB2 += __shfl_xor_sync(0xffffffffu, sB2, 1);
    if (h == 0) {
        smf[R1_OFF + nrow] = ssa + 2.0f * EPSV * sa;
        smf[R2_OFF + nrow] = ssb - 2.0f * EPSV * sB2 + (float)DDIM * EPSV * EPSV;
    }
    __syncthreads();

    // ---- epilogue: d = sqrt(max(r1 + r2 - 2*dot, 0)), float2 stores ----
    float r1v[4][2];
#pragma unroll
    for (int mt = 0; mt < 4; mt++) {
        r1v[mt][0] = smf[R1_OFF + wm * 64 + mt * 16 + g];
        r1v[mt][1] = smf[R1_OFF + wm * 64 + mt * 16 + g + 8];
    }
    float2 r2v[4];
#pragma unroll
    for (int nt = 0; nt < 4; nt++)
        r2v[nt] = *reinterpret_cast<const float2*>(&smf[R2_OFF + wn * 32 + nt * 8 + klane]);

    float* Ob = out + ((size_t)(b * LDIM + m0)) * LDIM + n0;
#pragma unroll
    for (int mt = 0; mt < 4; mt++) {
#pragma unroll
        for (int nt = 0; nt < 4; nt++) {
            const int col  = wn * 32 + nt * 8 + klane;
            const int row0 = wm * 64 + mt * 16 + g;
            float2 v0, v1;
            v0.x = fsqrt_fast(fmaxf(r1v[mt][0] + r2v[nt].x - 2.0f * acc[mt][nt][0], 0.f));
            v0.y = fsqrt_fast(fmaxf(r1v[mt][0] + r2v[nt].y - 2.0f * acc[mt][nt][1], 0.f));
            v1.x = fsqrt_fast(fmaxf(r1v[mt][1] + r2v[nt].x - 2.0f * acc[mt][nt][2], 0.f));
            v1.y = fsqrt_fast(fmaxf(r1v[mt][1] + r2v[nt].y - 2.0f * acc[mt][nt][3], 0.f));
            *reinterpret_cast<float2*>(Ob + (size_t)row0 * LDIM + col)       = v0;
            *reinterpret_cast<float2*>(Ob + (size_t)(row0 + 8) * LDIM + col) = v1;
        }
    }
}

// ---------------------------------------------------------------------------
extern "C" void kernel_launch(void* const* d_in, const int* in_sizes, int n_in,
                              void* d_out, int out_size) {
    const float* A = (const float*)d_in[0];
    const float* B = (const float*)d_in[1];
    float* out = (float*)d_out;
    (void)in_sizes; (void)n_in; (void)out_size;

    cudaFuncSetAttribute(dist_tf32_kernel,
                         cudaFuncAttributeMaxDynamicSharedMemorySize, SMEM_BYTES);
    dim3 grid(LDIM / CTN, LDIM / CTM, BATCH);
    dist_tf32_kernel<<<grid, 256, SMEM_BYTES>>>(A, B, out);
}

// round 8
// speedup vs baseline: 1.4585x; 1.3448x over previous
#include <cuda_runtime.h>
#include <cuda_fp16.h>
#include <math.h>
#include <stdint.h>

// Problem shape (fixed): B=512, L=512, D=256, fp32.
#define BATCH 512
#define LDIM  512
#define DDIM  256
#define EPSV  1e-6f

// ---------------- scratch (device globals; allocation-free) ----------------
__device__ unsigned short g_A16[(size_t)BATCH * LDIM * DDIM];  // 134MB, pre-swizzled fp16
__device__ unsigned short g_B16[(size_t)BATCH * LDIM * DDIM];  // 134MB
__device__ float g_r1[BATCH * LDIM];
__device__ float g_r2[BATCH * LDIM];

// ---------------- helpers ----------------
__device__ __forceinline__ uint32_t smem_u32(const void* p) {
    uint32_t a;
    asm("{ .reg .u64 t; cvta.to.shared.u64 t, %1; cvt.u32.u64 %0, t; }" : "=r"(a) : "l"(p));
    return a;
}
__device__ __forceinline__ float fsqrt_fast(float x) {
    float y; asm("sqrt.approx.f32 %0, %1;" : "=f"(y) : "f"(x)); return y;
}
__device__ __forceinline__ void cp16(uint32_t saddr, const void* g) {
    asm volatile("cp.async.cg.shared.global [%0], [%1], 16;" :: "r"(saddr), "l"(g));
}
__device__ __forceinline__ void cp_commit() { asm volatile("cp.async.commit_group;"); }
__device__ __forceinline__ void cp_wait1()  { asm volatile("cp.async.wait_group 1;" ::: "memory"); }
__device__ __forceinline__ void cp_wait0()  { asm volatile("cp.async.wait_group 0;" ::: "memory"); }

#define LDS64(v, addr) \
    asm volatile("ld.shared.v2.b32 {%0,%1}, [%2];" : "=r"((v).x), "=r"((v).y) : "r"(addr))

__device__ __forceinline__ void mma_f16(float* c,
                                        uint32_t a0, uint32_t a1, uint32_t a2, uint32_t a3,
                                        uint32_t b0, uint32_t b1) {
    asm volatile(
        "mma.sync.aligned.m16n8k16.row.col.f32.f16.f16.f32 "
        "{%0,%1,%2,%3}, {%4,%5,%6,%7}, {%8,%9}, {%0,%1,%2,%3};"
        : "+f"(c[0]), "+f"(c[1]), "+f"(c[2]), "+f"(c[3])
        : "r"(a0), "r"(a1), "r"(a2), "r"(a3), "r"(b0), "r"(b1));
}

// ---------------------------------------------------------------------------
// Pre-pass: one warp per row. Exact fp32 norms + fp16 conversion with the
// tile swizzle pre-applied (8B-chunk c -> c ^ key(row), key=((r&3)<<2)|((r>>2&1)<<1),
// applied within each 128B (k64) section of the 512B row).
// ---------------------------------------------------------------------------
__global__ __launch_bounds__(256)
void prep_kernel(const float* __restrict__ A, const float* __restrict__ B) {
    const int gw   = (int)((blockIdx.x * 256 + threadIdx.x) >> 5);
    const int lane = threadIdx.x & 31;
    const int isB  = (gw >= BATCH * LDIM);
    const int row  = isB ? gw - BATCH * LDIM : gw;

    const float* src = (isB ? B : A) + (size_t)row * DDIM + lane * 8;
    float4 v0 = *reinterpret_cast<const float4*>(src);
    float4 v1 = *reinterpret_cast<const float4*>(src + 4);

    float ss = 0.f, s = 0.f;
    ss = fmaf(v0.x, v0.x, ss); ss = fmaf(v0.y, v0.y, ss);
    ss = fmaf(v0.z, v0.z, ss); ss = fmaf(v0.w, v0.w, ss);
    ss = fmaf(v1.x, v1.x, ss); ss = fmaf(v1.y, v1.y, ss);
    ss = fmaf(v1.z, v1.z, ss); ss = fmaf(v1.w, v1.w, ss);
    s = v0.x + v0.y + v0.z + v0.w + v1.x + v1.y + v1.z + v1.w;
#pragma unroll
    for (int off = 16; off > 0; off >>= 1) {
        ss += __shfl_xor_sync(0xffffffffu, ss, off);
        s  += __shfl_xor_sync(0xffffffffu, s, off);
    }
    if (lane == 0) {
        if (isB) g_r2[row] = ss - 2.0f * EPSV * s + (float)DDIM * EPSV * EPSV;
        else     g_r1[row] = ss + 2.0f * EPSV * s;
    }

    // convert 8 floats -> 8 halfs (16B), store at swizzled position
    __half2 h0 = __floats2half2_rn(v0.x, v0.y);
    __half2 h1 = __floats2half2_rn(v0.z, v0.w);
    __half2 h2 = __floats2half2_rn(v1.x, v1.y);
    __half2 h3 = __floats2half2_rn(v1.z, v1.w);
    uint4 pk;
    pk.x = *reinterpret_cast<uint32_t*>(&h0);
    pk.y = *reinterpret_cast<uint32_t*>(&h1);
    pk.z = *reinterpret_cast<uint32_t*>(&h2);
    pk.w = *reinterpret_cast<uint32_t*>(&h3);

    const int key = ((row & 3) << 2) | (((row >> 2) & 1) << 1);
    const int sec = lane >> 3;            // 128B section within the row
    const int ci  = (2 * lane) & 15;      // 8B chunk index within section (even)
    char* dst = (char*)(isB ? g_B16 : g_A16) + (size_t)row * 512 + sec * 128 + ((ci ^ key) << 3);
    *reinterpret_cast<uint4*>(dst) = pk;
}

// ---------------------------------------------------------------------------
// Main: fp16 m16n8k16 GEMM, 128x128 CTA tile, k64 chunks, 3-stage cp.async.
// smem: 3 stages x (A 16KB + B 16KB) = 96KB.
// ---------------------------------------------------------------------------
#define TILEB 16384
#define STGB  (2*TILEB)
#define SMEM_BYTES (3*STGB)   // 98304

__global__ __launch_bounds__(256, 2)
void dist_f16_kernel(float* __restrict__ out) {
    extern __shared__ char smem[];
    const uint32_t sb = smem_u32(smem);

    const int tid = threadIdx.x;
    const int wid = tid >> 5, lid = tid & 31;
    const int b  = blockIdx.z;
    const int m0 = blockIdx.y * 128;
    const int n0 = blockIdx.x * 128;

    // ---- cp.async mapping: thread -> (row tid>>3 + 32t, 16B chunk tid&7) ----
    const int crow = tid >> 3;
    const int cc   = tid & 7;
    const char* Asrc = (const char*)g_A16 + (size_t)(b * LDIM + m0 + crow) * 512 + cc * 16;
    const char* Bsrc = (const char*)g_B16 + (size_t)(b * LDIM + n0 + crow) * 512 + cc * 16;
    const uint32_t sdst = sb + (uint32_t)(crow * 128 + cc * 16);

    // ---- compute mapping: 2x4 warp grid, 64x32 warp tiles ----
    const int wm = wid >> 2, wn = wid & 3;
    const int g = lid >> 2, tig = lid & 3;
    const int arow0 = wm * 64 + g;
    const int brow0 = wn * 32 + g;
    // intra-row swizzled offsets (scratch is pre-swizzled):
    const int txa = (tig ^ (((g >> 2) & 1) << 1)) << 3;  // bytes
    const int gl2 = g & 3;
    const uint32_t aBase = sb + (uint32_t)(arow0 * 128 + txa);
    const uint32_t bBase = sb + TILEB + (uint32_t)(brow0 * 128 + txa);

    float acc[4][4][4];
#pragma unroll
    for (int mt = 0; mt < 4; mt++)
#pragma unroll
        for (int nt = 0; nt < 4; nt++)
#pragma unroll
            for (int r = 0; r < 4; r++) acc[mt][nt][r] = 0.f;

    // ---- prologue: stage chunks 0 and 1 ----
#pragma unroll
    for (int s = 0; s < 2; s++) {
#pragma unroll
        for (int t = 0; t < 4; t++) {
            cp16(sdst + s * STGB + t * 4096,         Asrc + (size_t)(t * 32) * 512 + s * 128);
            cp16(sdst + s * STGB + TILEB + t * 4096, Bsrc + (size_t)(t * 32) * 512 + s * 128);
        }
        cp_commit();
    }

#pragma unroll 1
    for (int kt = 0; kt < 4; kt++) {
        if (kt == 3) cp_wait0(); else cp_wait1();
        __syncthreads();

        if (kt + 2 < 4) {
            const uint32_t cs = (uint32_t)(((kt + 2) % 3) * STGB);
#pragma unroll
            for (int t = 0; t < 4; t++) {
                cp16(sdst + cs + t * 4096,         Asrc + (size_t)(t * 32) * 512 + (kt + 2) * 128);
                cp16(sdst + cs + TILEB + t * 4096, Bsrc + (size_t)(t * 32) * 512 + (kt + 2) * 128);
            }
            cp_commit();
        }

        const uint32_t so = (uint32_t)((kt % 3) * STGB);
        const uint32_t sA = aBase + so;
        const uint32_t sB = bBase + so;

        // ---- 4 k16 blocks; thread tig owns true-k quad {16blk+4tig..+3} ----
#pragma unroll
        for (int blk = 0; blk < 4; blk++) {
            const uint32_t bo = (uint32_t)((blk ^ gl2) << 5);
            uint2 bf[4];
#pragma unroll
            for (int nt = 0; nt < 4; nt++)
                LDS64(bf[nt], sB + bo + nt * 8 * 128);
#pragma unroll
            for (int mt = 0; mt < 4; mt++) {
                uint2 alo, ahi;
                LDS64(alo, sA + bo + mt * 16 * 128);
                LDS64(ahi, sA + bo + mt * 16 * 128 + 8 * 128);
#pragma unroll
                for (int nt = 0; nt < 4; nt++)
                    mma_f16(acc[mt][nt], alo.x, ahi.x, alo.y, ahi.y, bf[nt].x, bf[nt].y);
            }
        }
    }

    // ---- epilogue: d = sqrt(max(r1 + r2 - 2*dot, 0)) ----
    const int klane = 2 * tig;
    const float* R1 = g_r1 + b * LDIM + m0;
    const float* R2 = g_r2 + b * LDIM + n0;
    float r1v[4][2];
#pragma unroll
    for (int mt = 0; mt < 4; mt++) {
        r1v[mt][0] = R1[wm * 64 + mt * 16 + g];
        r1v[mt][1] = R1[wm * 64 + mt * 16 + g + 8];
    }
    float2 r2v[4];
#pragma unroll
    for (int nt = 0; nt < 4; nt++)
        r2v[nt] = *reinterpret_cast<const float2*>(R2 + wn * 32 + nt * 8 + klane);

    float* Ob = out + ((size_t)(b * LDIM + m0)) * LDIM + n0;
#pragma unroll
    for (int mt = 0; mt < 4; mt++) {
#pragma unroll
        for (int nt = 0; nt < 4; nt++) {
            const int col  = wn * 32 + nt * 8 + klane;
            const int row0 = wm * 64 + mt * 16 + g;
            float2 v0, v1;
            v0.x = fsqrt_fast(fmaxf(r1v[mt][0] + r2v[nt].x - 2.0f * acc[mt][nt][0], 0.f));
            v0.y = fsqrt_fast(fmaxf(r1v[mt][0] + r2v[nt].y - 2.0f * acc[mt][nt][1], 0.f));
            v1.x = fsqrt_fast(fmaxf(r1v[mt][1] + r2v[nt].x - 2.0f * acc[mt][nt][2], 0.f));
            v1.y = fsqrt_fast(fmaxf(r1v[mt][1] + r2v[nt].y - 2.0f * acc[mt][nt][3], 0.f));
            *reinterpret_cast<float2*>(Ob + (size_t)row0 * LDIM + col)       = v0;
            *reinterpret_cast<float2*>(Ob + (size_t)(row0 + 8) * LDIM + col) = v1;
        }
    }
}

// ---------------------------------------------------------------------------
extern "C" void kernel_launch(void* const* d_in, const int* in_sizes, int n_in,
                              void* d_out, int out_size) {
    const float* A = (const float*)d_in[0];
    const float* B = (const float*)d_in[1];
    float* out = (float*)d_out;
    (void)in_sizes; (void)n_in; (void)out_size;

    // pre-pass: 2*512*512 rows, 1 warp/row, 8 warps/block
    prep_kernel<<<(2 * BATCH * LDIM) / 8, 256>>>(A, B);

    cudaFuncSetAttribute(dist_f16_kernel,
                         cudaFuncAttributeMaxDynamicSharedMemorySize, SMEM_BYTES);
    dim3 grid(LDIM / 128, LDIM / 128, BATCH);
    dist_f16_kernel<<<grid, 256, SMEM_BYTES>>>(out);
}